// round 1
// baseline (speedup 1.0000x reference)
#include <cuda_runtime.h>
#include <cuda_bf16.h>
#include <math.h>

// ---------------- problem constants ----------------
#define B_  32
#define C_  3
#define IMG_ 224
#define P_  16
#define W_  768
#define L_  12
#define H_  12
#define S_  197          // 14*14 + 1
#define HD_ 64
#define FF_ 3072
#define E_  512
#define NPATCH_ 196
#define BSW_ (B_*S_*W_)  // 4,841,472

// ---------------- scratch (no cudaMalloc allowed) ----------------
__device__ float g_h   [BSW_];
__device__ float g_y   [BSW_];
__device__ float g_q   [BSW_];
__device__ float g_k   [BSW_];
__device__ float g_v   [BSW_];
__device__ float g_o   [BSW_];
__device__ float g_att [B_*H_*S_*S_];        // 14,902,656
__device__ float g_ff  [B_*S_*FF_];          // 19,365,888
__device__ float g_im2col[B_*NPATCH_*W_];    // 4,816,896
__device__ float g_tok [B_*NPATCH_*W_];
__device__ float g_cls [B_*W_];

// ---------------- generic 128x128x8 fp32 GEMM ----------------
// C[M,N] = op( A[M,K] @ B + bias ), B row-major [K,N] or (TRANSB) [N,K].
// N must be a multiple of 128 and K a multiple of 8 (true for all call sites).
// ACCUM: C += result (residual).  GELU: exact gelu on (A@B + bias).
__device__ __forceinline__ float gelu_exact(float v) {
    return 0.5f * v * (1.0f + erff(v * 0.70710678118654752f));
}

template<int TRANSB, int HAS_BIAS, int ACCUM, int DO_GELU>
__global__ __launch_bounds__(256, 2)
void gemm128(const float* __restrict__ A, const float* __restrict__ Bm,
             const float* __restrict__ bias, float* __restrict__ C,
             int M, int N, int K)
{
    __shared__ float As[8][128];
    __shared__ float Bs[8][128];

    const int t  = threadIdx.x;
    const int m0 = blockIdx.y * 128;
    const int n0 = blockIdx.x * 128;

    float acc[8][8];
    #pragma unroll
    for (int i = 0; i < 8; i++)
        #pragma unroll
        for (int j = 0; j < 8; j++) acc[i][j] = 0.0f;

    // A tile load mapping: thread t loads float4 at (m = t>>1, k = (t&1)*4)
    const int am = t >> 1;
    const int ak = (t & 1) * 4;

    const int ty = t >> 4;   // 0..15
    const int tx = t & 15;   // 0..15

    for (int k0 = 0; k0 < K; k0 += 8) {
        // ---- load A (128 x 8), transposed into As[k][m]
        float4 av;
        const int gm = m0 + am;
        if (gm < M) av = *reinterpret_cast<const float4*>(A + (size_t)gm * K + k0 + ak);
        else        av = make_float4(0.f, 0.f, 0.f, 0.f);
        As[ak + 0][am] = av.x;
        As[ak + 1][am] = av.y;
        As[ak + 2][am] = av.z;
        As[ak + 3][am] = av.w;

        // ---- load B (8 x 128) into Bs[k][n]
        if (TRANSB) {
            const int nb = t >> 1, kb = (t & 1) * 4;
            float4 bv = *reinterpret_cast<const float4*>(Bm + (size_t)(n0 + nb) * K + k0 + kb);
            Bs[kb + 0][nb] = bv.x;
            Bs[kb + 1][nb] = bv.y;
            Bs[kb + 2][nb] = bv.z;
            Bs[kb + 3][nb] = bv.w;
        } else {
            const int kb = t >> 5, nb = (t & 31) * 4;
            float4 bv = *reinterpret_cast<const float4*>(Bm + (size_t)(k0 + kb) * N + n0 + nb);
            *reinterpret_cast<float4*>(&Bs[kb][nb]) = bv;
        }
        __syncthreads();

        #pragma unroll
        for (int kk = 0; kk < 8; kk++) {
            float4 a0 = *reinterpret_cast<float4*>(&As[kk][ty * 8]);
            float4 a1 = *reinterpret_cast<float4*>(&As[kk][ty * 8 + 4]);
            float4 b0 = *reinterpret_cast<float4*>(&Bs[kk][tx * 8]);
            float4 b1 = *reinterpret_cast<float4*>(&Bs[kk][tx * 8 + 4]);
            float a[8] = {a0.x, a0.y, a0.z, a0.w, a1.x, a1.y, a1.z, a1.w};
            float b[8] = {b0.x, b0.y, b0.z, b0.w, b1.x, b1.y, b1.z, b1.w};
            #pragma unroll
            for (int i = 0; i < 8; i++)
                #pragma unroll
                for (int j = 0; j < 8; j++)
                    acc[i][j] = fmaf(a[i], b[j], acc[i][j]);
        }
        __syncthreads();
    }

    // ---- epilogue
    #pragma unroll
    for (int i = 0; i < 8; i++) {
        const int gm = m0 + ty * 8 + i;
        if (gm >= M) continue;
        #pragma unroll
        for (int j = 0; j < 8; j++) {
            const int gn = n0 + tx * 8 + j;
            float v = acc[i][j];
            if (HAS_BIAS) v += bias[gn];
            if (DO_GELU)  v = gelu_exact(v);
            if (ACCUM)    v += C[(size_t)gm * N + gn];
            C[(size_t)gm * N + gn] = v;
        }
    }
}

// ---------------- im2col (conv 16x16 stride 16 -> GEMM) ----------------
__global__ void im2col_kernel(const float* __restrict__ x, float* __restrict__ out)
{
    const int total = B_ * NPATCH_ * W_;   // W_ = C_*P_*P_ = 768
    int idx = blockIdx.x * 256 + threadIdx.x;
    if (idx >= total) return;
    const int kk = idx % W_;
    const int r  = idx / W_;
    const int b  = r / NPATCH_;
    const int p  = r % NPATCH_;
    const int ph = p / 14, pw = p % 14;
    const int c  = kk >> 8;
    const int py = (kk >> 4) & 15;
    const int px = kk & 15;
    out[idx] = x[(((size_t)b * C_ + c) * IMG_ + ph * P_ + py) * IMG_ + pw * P_ + px];
}

// ---------------- assemble h = [cls; tokens] + pe ----------------
__global__ void assemble_kernel(const float* __restrict__ tok,
                                const float* __restrict__ cls,
                                const float* __restrict__ pe,
                                float* __restrict__ h)
{
    int idx = blockIdx.x * 256 + threadIdx.x;
    if (idx >= BSW_) return;
    const int w   = idx % W_;
    const int bs  = idx / W_;
    const int s   = bs % S_;
    const int b   = bs / S_;
    float v;
    if (s == 0) v = cls[w];
    else        v = tok[((size_t)b * NPATCH_ + (s - 1)) * W_ + w];
    h[idx] = v + pe[(size_t)s * W_ + w];
}

// ---------------- layernorm (row = B*S, width 768) ----------------
__global__ void layernorm_kernel(const float* __restrict__ x,
                                 const float* __restrict__ gamma,
                                 const float* __restrict__ beta,
                                 float* __restrict__ y)
{
    const int row = blockIdx.x;
    const float* xr = x + (size_t)row * W_;
    float s = 0.f, s2 = 0.f;
    for (int i = threadIdx.x; i < W_; i += 256) {
        float v = xr[i];
        s += v; s2 += v * v;
    }
    // warp reduce
    for (int off = 16; off > 0; off >>= 1) {
        s  += __shfl_down_sync(0xffffffffu, s, off);
        s2 += __shfl_down_sync(0xffffffffu, s2, off);
    }
    __shared__ float rs[8], rs2[8];
    const int warp = threadIdx.x >> 5, lane = threadIdx.x & 31;
    if (lane == 0) { rs[warp] = s; rs2[warp] = s2; }
    __syncthreads();
    __shared__ float mean_sh, inv_sh;
    if (threadIdx.x == 0) {
        float ts = 0.f, ts2 = 0.f;
        for (int i = 0; i < 8; i++) { ts += rs[i]; ts2 += rs2[i]; }
        float mean = ts * (1.0f / W_);
        float var  = ts2 * (1.0f / W_) - mean * mean;
        mean_sh = mean;
        inv_sh  = rsqrtf(var + 1e-5f);
    }
    __syncthreads();
    const float mean = mean_sh, inv = inv_sh;
    float* yr = y + (size_t)row * W_;
    for (int i = threadIdx.x; i < W_; i += 256)
        yr[i] = (xr[i] - mean) * inv * gamma[i] + beta[i];
}

// ---------------- attention: scores = q . k^T (per b,h) ----------------
__global__ void attn_scores_kernel(const float* __restrict__ q,
                                   const float* __restrict__ k,
                                   float* __restrict__ att)
{
    const int z  = blockIdx.z;           // b*H + h
    const int b  = z / H_, h = z % H_;
    const int s0 = blockIdx.y * 16;
    const int t0 = blockIdx.x * 16;

    __shared__ float qs[16][65];
    __shared__ float ks[16][65];

    const int t = threadIdx.x;           // 256
    const int r = t >> 4;
    const int c = (t & 15) * 4;

    const float* qbase = q + (size_t)b * S_ * W_ + h * HD_;
    const float* kbase = k + (size_t)b * S_ * W_ + h * HD_;

    const int gs = s0 + r;
    float4 qv = (gs < S_) ? *reinterpret_cast<const float4*>(qbase + (size_t)gs * W_ + c)
                          : make_float4(0.f, 0.f, 0.f, 0.f);
    qs[r][c] = qv.x; qs[r][c + 1] = qv.y; qs[r][c + 2] = qv.z; qs[r][c + 3] = qv.w;

    const int gt = t0 + r;
    float4 kv = (gt < S_) ? *reinterpret_cast<const float4*>(kbase + (size_t)gt * W_ + c)
                          : make_float4(0.f, 0.f, 0.f, 0.f);
    ks[r][c] = kv.x; ks[r][c + 1] = kv.y; ks[r][c + 2] = kv.z; ks[r][c + 3] = kv.w;
    __syncthreads();

    const int si = t >> 4, ti = t & 15;
    float acc = 0.f;
    #pragma unroll
    for (int d = 0; d < HD_; d++)
        acc = fmaf(qs[si][d], ks[ti][d], acc);

    const int gs2 = s0 + si, gt2 = t0 + ti;
    if (gs2 < S_ && gt2 < S_)
        att[((size_t)z * S_ + gs2) * S_ + gt2] = acc;
}

// ---------------- softmax over last dim (scale 1/8 folded in) ----------------
__global__ void softmax_kernel(float* __restrict__ att, int nrows)
{
    const int warp = blockIdx.x * 4 + (threadIdx.x >> 5);
    const int lane = threadIdx.x & 31;
    if (warp >= nrows) return;
    float* row = att + (size_t)warp * S_;

    float mx = -1e30f;
    for (int i = lane; i < S_; i += 32) mx = fmaxf(mx, row[i]);
    for (int off = 16; off > 0; off >>= 1)
        mx = fmaxf(mx, __shfl_xor_sync(0xffffffffu, mx, off));

    float sum = 0.f;
    for (int i = lane; i < S_; i += 32) {
        float e = expf((row[i] - mx) * 0.125f);   // 1/sqrt(64)
        row[i] = e;
        sum += e;
    }
    for (int off = 16; off > 0; off >>= 1)
        sum += __shfl_xor_sync(0xffffffffu, sum, off);
    const float inv = 1.0f / sum;
    for (int i = lane; i < S_; i += 32) row[i] *= inv;
}

// ---------------- o = att @ v, written directly in [B,S,W] layout ----------------
__global__ void attn_av_kernel(const float* __restrict__ att,
                               const float* __restrict__ v,
                               float* __restrict__ o)
{
    const int z  = blockIdx.y;
    const int b  = z / H_, h = z % H_;
    const int s0 = blockIdx.x * 16;

    __shared__ float as_[16][17];
    __shared__ float vs[16][65];

    const int si = threadIdx.x >> 4;   // 0..15 (row within s-tile)
    const int dj = threadIdx.x & 15;   // 0..15 (4 d-values per thread)

    float acc0 = 0.f, acc1 = 0.f, acc2 = 0.f, acc3 = 0.f;
    const float* vbase = v + (size_t)b * S_ * W_ + h * HD_;

    for (int t0 = 0; t0 < S_; t0 += 16) {
        float a = 0.f;
        if (s0 + si < S_ && t0 + dj < S_)
            a = att[((size_t)z * S_ + s0 + si) * S_ + t0 + dj];
        as_[si][dj] = a;

        const int r = si, c = dj * 4;
        float4 vv = (t0 + r < S_) ? *reinterpret_cast<const float4*>(vbase + (size_t)(t0 + r) * W_ + c)
                                  : make_float4(0.f, 0.f, 0.f, 0.f);
        vs[r][c] = vv.x; vs[r][c + 1] = vv.y; vs[r][c + 2] = vv.z; vs[r][c + 3] = vv.w;
        __syncthreads();

        #pragma unroll
        for (int tt = 0; tt < 16; tt++) {
            const float a2 = as_[si][tt];
            acc0 = fmaf(a2, vs[tt][dj * 4 + 0], acc0);
            acc1 = fmaf(a2, vs[tt][dj * 4 + 1], acc1);
            acc2 = fmaf(a2, vs[tt][dj * 4 + 2], acc2);
            acc3 = fmaf(a2, vs[tt][dj * 4 + 3], acc3);
        }
        __syncthreads();
    }

    const int gs = s0 + si;
    if (gs < S_) {
        float* obase = o + (size_t)b * S_ * W_ + (size_t)gs * W_ + h * HD_ + dj * 4;
        obase[0] = acc0; obase[1] = acc1; obase[2] = acc2; obase[3] = acc3;
    }
}

// ---------------- gather h[:,0,:] ----------------
__global__ void gather_cls_kernel(const float* __restrict__ h, float* __restrict__ cls)
{
    int idx = blockIdx.x * 256 + threadIdx.x;
    if (idx >= B_ * W_) return;
    const int b = idx / W_, w = idx % W_;
    cls[idx] = h[(size_t)b * S_ * W_ + w];
}

// ---------------- L2 normalize rows of out[32,512] ----------------
__global__ void l2norm_kernel(float* __restrict__ out)
{
    const int row = blockIdx.x;
    float* r = out + (size_t)row * E_;
    float s = 0.f;
    for (int i = threadIdx.x; i < E_; i += 256) { float v = r[i]; s += v * v; }
    for (int off = 16; off > 0; off >>= 1) s += __shfl_down_sync(0xffffffffu, s, off);
    __shared__ float rs[8];
    const int warp = threadIdx.x >> 5, lane = threadIdx.x & 31;
    if (lane == 0) rs[warp] = s;
    __syncthreads();
    __shared__ float inv_sh;
    if (threadIdx.x == 0) {
        float ts = 0.f;
        for (int i = 0; i < 8; i++) ts += rs[i];
        inv_sh = rsqrtf(ts);
    }
    __syncthreads();
    const float inv = inv_sh;
    for (int i = threadIdx.x; i < E_; i += 256) r[i] *= inv;
}

// ---------------- launch ----------------
extern "C" void kernel_launch(void* const* d_in, const int* in_sizes, int n_in,
                              void* d_out, int out_size)
{
    (void)in_sizes; (void)n_in; (void)out_size;

    const float* x       = (const float*)d_in[0];
    const float* conv_w  = (const float*)d_in[1];
    const float* conv_b  = (const float*)d_in[2];
    const float* cls_tok = (const float*)d_in[3];
    const float* pe      = (const float*)d_in[4];
    const float* ln1_g   = (const float*)d_in[5];
    const float* ln1_b   = (const float*)d_in[6];
    const float* wq      = (const float*)d_in[7];
    const float* bq      = (const float*)d_in[8];
    const float* wk      = (const float*)d_in[9];
    const float* bk      = (const float*)d_in[10];
    const float* wv      = (const float*)d_in[11];
    const float* bv      = (const float*)d_in[12];
    const float* wo      = (const float*)d_in[13];
    const float* bo      = (const float*)d_in[14];
    const float* ln2_g   = (const float*)d_in[15];
    const float* ln2_b   = (const float*)d_in[16];
    const float* w1      = (const float*)d_in[17];
    const float* b1      = (const float*)d_in[18];
    const float* w2      = (const float*)d_in[19];
    const float* b2      = (const float*)d_in[20];
    const float* proj    = (const float*)d_in[21];
    float* out           = (float*)d_out;

    float *h, *y, *q, *k, *v, *o, *att, *ff, *i2c, *tok, *cls;
    cudaGetSymbolAddress((void**)&h,   g_h);
    cudaGetSymbolAddress((void**)&y,   g_y);
    cudaGetSymbolAddress((void**)&q,   g_q);
    cudaGetSymbolAddress((void**)&k,   g_k);
    cudaGetSymbolAddress((void**)&v,   g_v);
    cudaGetSymbolAddress((void**)&o,   g_o);
    cudaGetSymbolAddress((void**)&att, g_att);
    cudaGetSymbolAddress((void**)&ff,  g_ff);
    cudaGetSymbolAddress((void**)&i2c, g_im2col);
    cudaGetSymbolAddress((void**)&tok, g_tok);
    cudaGetSymbolAddress((void**)&cls, g_cls);

    const int M  = B_ * S_;          // 6304
    const int Mp = B_ * NPATCH_;     // 6272

    // --- patch embedding ---
    {
        const int total = Mp * W_;
        im2col_kernel<<<(total + 255) / 256, 256>>>(x, i2c);
        dim3 grid(W_ / 128, (Mp + 127) / 128);
        gemm128<1, 1, 0, 0><<<grid, 256>>>(i2c, conv_w, conv_b, tok, Mp, W_, W_);
        assemble_kernel<<<(BSW_ + 255) / 256, 256>>>(tok, cls_tok, pe, h);
    }

    const int nrows_att = B_ * H_ * S_;   // 75648
    dim3 gridW (W_  / 128, (M + 127) / 128);   // (6, 50)
    dim3 gridFF(FF_ / 128, (M + 127) / 128);   // (24, 50)
    dim3 gridSc(13, 13, B_ * H_);
    dim3 gridAv(13, B_ * H_);

    for (int l = 0; l < L_; l++) {
        const size_t wOff = (size_t)l * W_ * W_;
        const size_t bOff = (size_t)l * W_;

        // LN1
        layernorm_kernel<<<M, 256>>>(h, ln1_g + bOff, ln1_b + bOff, y);
        // QKV
        gemm128<0, 1, 0, 0><<<gridW, 256>>>(y, wq + wOff, bq + bOff, q, M, W_, W_);
        gemm128<0, 1, 0, 0><<<gridW, 256>>>(y, wk + wOff, bk + bOff, k, M, W_, W_);
        gemm128<0, 1, 0, 0><<<gridW, 256>>>(y, wv + wOff, bv + bOff, v, M, W_, W_);
        // attention
        attn_scores_kernel<<<gridSc, 256>>>(q, k, att);
        softmax_kernel<<<(nrows_att + 3) / 4, 128>>>(att, nrows_att);
        attn_av_kernel<<<gridAv, 256>>>(att, v, o);
        // h += o @ Wo + bo
        gemm128<0, 1, 1, 0><<<gridW, 256>>>(o, wo + wOff, bo + bOff, h, M, W_, W_);
        // LN2 + MLP
        layernorm_kernel<<<M, 256>>>(h, ln2_g + bOff, ln2_b + bOff, y);
        gemm128<0, 1, 0, 1><<<gridFF, 256>>>(y, w1 + (size_t)l * W_ * FF_,
                                             b1 + (size_t)l * FF_, ff, M, FF_, W_);
        gemm128<0, 1, 1, 0><<<gridW, 256>>>(ff, w2 + (size_t)l * FF_ * W_,
                                            b2 + bOff, h, M, W_, FF_);
    }

    // --- head ---
    gather_cls_kernel<<<(B_ * W_ + 255) / 256, 256>>>(h, cls);
    {
        dim3 grid(E_ / 128, 1);
        gemm128<0, 0, 0, 0><<<grid, 256>>>(cls, proj, nullptr, out, B_, E_, W_);
    }
    l2norm_kernel<<<B_, 256>>>(out);
}

// round 2
// speedup vs baseline: 2.0339x; 2.0339x over previous
#include <cuda_runtime.h>
#include <cuda_bf16.h>
#include <math.h>

// ---------------- problem constants ----------------
#define B_  32
#define C_  3
#define IMG_ 224
#define P_  16
#define W_  768
#define L_  12
#define H_  12
#define S_  197          // 14*14 + 1
#define HD_ 64
#define FF_ 3072
#define E_  512
#define NPATCH_ 196
#define BSW_ (B_*S_*W_)  // 4,841,472

// ---------------- scratch (no cudaMalloc allowed) ----------------
__device__ float g_h   [BSW_];
__device__ float g_y   [BSW_];
__device__ float g_q   [BSW_];
__device__ float g_k   [BSW_];
__device__ float g_v   [BSW_];
__device__ float g_o   [BSW_];
__device__ float g_att [B_*H_*S_*S_];        // 14,902,656
__device__ float g_ff  [B_*S_*FF_];          // 19,365,888
__device__ float g_im2col[B_*NPATCH_*W_];    // 4,816,896
__device__ float g_tok [B_*NPATCH_*W_];
__device__ float g_cls [B_*W_];

__device__ __forceinline__ float gelu_exact(float v) {
    return 0.5f * v * (1.0f + erff(v * 0.70710678118654752f));
}

__device__ __forceinline__ unsigned f2tf(float x) {
    unsigned u;
    asm("cvt.rna.tf32.f32 %0, %1;" : "=r"(u) : "f"(x));
    return u;
}

// ---------------- tensor-core TF32 GEMM, 128x128x16 tile ----------------
// C[M,N] = op( A[M,K] @ B + bias ). B row-major [K,N] or (TRANSB) [N,K].
// N % 128 == 0, K % 16 == 0 at every call site. M arbitrary (guarded).
// 8 warps, each computes 64x32 via m16n8k8 tf32 mma (4 mtiles x 4 ntiles).
#define SROW 136   // padded smem row stride (bank-conflict-free fragments)

template<int TRANSB, int HAS_BIAS, int ACCUM, int DO_GELU>
__global__ __launch_bounds__(256)
void gemm_tc(const float* __restrict__ A, const float* __restrict__ Bm,
             const float* __restrict__ bias, float* __restrict__ C,
             int M, int N, int K)
{
    __shared__ float sA[2 * 16 * SROW];
    __shared__ float sB[2 * 16 * SROW];

    const int t    = threadIdx.x;
    const int m0   = blockIdx.y * 128;
    const int n0   = blockIdx.x * 128;
    const int warp = t >> 5, lane = t & 31;
    const int wm   = (warp >> 2) * 64;   // 0 or 64
    const int wn   = (warp & 3) * 32;    // 0,32,64,96
    const int grp  = lane >> 2;          // 0..7
    const int idx  = lane & 3;           // 0..3

    float acc[4][4][4];
    #pragma unroll
    for (int a = 0; a < 4; a++)
        #pragma unroll
        for (int b = 0; b < 4; b++)
            #pragma unroll
            for (int c = 0; c < 4; c++) acc[a][b][c] = 0.0f;

    const int ar  = t >> 2;        // 0..63
    const int akc = (t & 3) * 4;   // 0,4,8,12

    float4 aR[2], bR[2];

    auto loadRegs = [&](int k0) {
        #pragma unroll
        for (int it = 0; it < 2; it++) {
            const int gm = m0 + ar + 64 * it;
            aR[it] = (gm < M) ? *reinterpret_cast<const float4*>(A + (size_t)gm * K + k0 + akc)
                              : make_float4(0.f, 0.f, 0.f, 0.f);
        }
        if (TRANSB) {
            #pragma unroll
            for (int it = 0; it < 2; it++) {
                const int gn = n0 + ar + 64 * it;
                bR[it] = *reinterpret_cast<const float4*>(Bm + (size_t)gn * K + k0 + akc);
            }
        } else {
            #pragma unroll
            for (int it = 0; it < 2; it++) {
                const int gk = k0 + (t >> 5) + 8 * it;
                bR[it] = *reinterpret_cast<const float4*>(Bm + (size_t)gk * N + n0 + (t & 31) * 4);
            }
        }
    };

    auto storeRegs = [&](int buf) {
        float* pa = sA + buf * 16 * SROW;
        float* pb = sB + buf * 16 * SROW;
        #pragma unroll
        for (int it = 0; it < 2; it++) {
            float v[4] = {aR[it].x, aR[it].y, aR[it].z, aR[it].w};
            #pragma unroll
            for (int j = 0; j < 4; j++)
                pa[(akc + j) * SROW + ar + 64 * it] = __uint_as_float(f2tf(v[j]));
        }
        if (TRANSB) {
            #pragma unroll
            for (int it = 0; it < 2; it++) {
                float v[4] = {bR[it].x, bR[it].y, bR[it].z, bR[it].w};
                #pragma unroll
                for (int j = 0; j < 4; j++)
                    pb[(akc + j) * SROW + ar + 64 * it] = __uint_as_float(f2tf(v[j]));
            }
        } else {
            #pragma unroll
            for (int it = 0; it < 2; it++) {
                float v[4] = {bR[it].x, bR[it].y, bR[it].z, bR[it].w};
                const int bk = (t >> 5) + 8 * it;
                const int bn = (t & 31) * 4;
                #pragma unroll
                for (int j = 0; j < 4; j++)
                    pb[bk * SROW + bn + j] = __uint_as_float(f2tf(v[j]));
            }
        }
    };

    loadRegs(0);
    storeRegs(0);
    __syncthreads();

    const int nk = K / 16;
    for (int kt = 0; kt < nk; kt++) {
        const int buf = kt & 1;
        if (kt + 1 < nk) loadRegs((kt + 1) * 16);

        const float* pa = sA + buf * 16 * SROW;
        const float* pb = sB + buf * 16 * SROW;

        #pragma unroll
        for (int kk = 0; kk < 16; kk += 8) {
            unsigned af[4][4], bf[4][2];
            #pragma unroll
            for (int mt = 0; mt < 4; mt++) {
                const float* p = pa + (kk + idx) * SROW + wm + mt * 16 + grp;
                af[mt][0] = __float_as_uint(p[0]);
                af[mt][1] = __float_as_uint(p[8]);
                af[mt][2] = __float_as_uint(p[4 * SROW]);
                af[mt][3] = __float_as_uint(p[4 * SROW + 8]);
            }
            #pragma unroll
            for (int nt = 0; nt < 4; nt++) {
                const float* p = pb + (kk + idx) * SROW + wn + nt * 8 + grp;
                bf[nt][0] = __float_as_uint(p[0]);
                bf[nt][1] = __float_as_uint(p[4 * SROW]);
            }
            #pragma unroll
            for (int mt = 0; mt < 4; mt++)
                #pragma unroll
                for (int nt = 0; nt < 4; nt++)
                    asm volatile(
                        "mma.sync.aligned.m16n8k8.row.col.f32.tf32.tf32.f32 "
                        "{%0,%1,%2,%3}, {%4,%5,%6,%7}, {%8,%9}, {%0,%1,%2,%3};"
                        : "+f"(acc[mt][nt][0]), "+f"(acc[mt][nt][1]),
                          "+f"(acc[mt][nt][2]), "+f"(acc[mt][nt][3])
                        : "r"(af[mt][0]), "r"(af[mt][1]), "r"(af[mt][2]), "r"(af[mt][3]),
                          "r"(bf[nt][0]), "r"(bf[nt][1]));
        }

        if (kt + 1 < nk) storeRegs(buf ^ 1);
        __syncthreads();
    }

    // ---- epilogue
    #pragma unroll
    for (int mt = 0; mt < 4; mt++) {
        const int r0 = m0 + wm + mt * 16 + grp;
        #pragma unroll
        for (int half = 0; half < 2; half++) {
            const int gm = r0 + half * 8;
            if (gm >= M) continue;
            #pragma unroll
            for (int nt = 0; nt < 4; nt++) {
                const int gn = n0 + wn + nt * 8 + idx * 2;
                float v0 = acc[mt][nt][half * 2 + 0];
                float v1 = acc[mt][nt][half * 2 + 1];
                if (HAS_BIAS) { v0 += bias[gn]; v1 += bias[gn + 1]; }
                if (DO_GELU)  { v0 = gelu_exact(v0); v1 = gelu_exact(v1); }
                float* p = C + (size_t)gm * N + gn;
                if (ACCUM) {
                    float2 old = *reinterpret_cast<float2*>(p);
                    v0 += old.x; v1 += old.y;
                }
                *reinterpret_cast<float2*>(p) = make_float2(v0, v1);
            }
        }
    }
}

// ---------------- im2col (conv 16x16 stride 16 -> GEMM) ----------------
__global__ void im2col_kernel(const float* __restrict__ x, float* __restrict__ out)
{
    const int total = B_ * NPATCH_ * W_;
    int idx = blockIdx.x * 256 + threadIdx.x;
    if (idx >= total) return;
    const int kk = idx % W_;
    const int r  = idx / W_;
    const int b  = r / NPATCH_;
    const int p  = r % NPATCH_;
    const int ph = p / 14, pw = p % 14;
    const int c  = kk >> 8;
    const int py = (kk >> 4) & 15;
    const int px = kk & 15;
    out[idx] = x[(((size_t)b * C_ + c) * IMG_ + ph * P_ + py) * IMG_ + pw * P_ + px];
}

// ---------------- assemble h = [cls; tokens] + pe ----------------
__global__ void assemble_kernel(const float* __restrict__ tok,
                                const float* __restrict__ cls,
                                const float* __restrict__ pe,
                                float* __restrict__ h)
{
    int idx = blockIdx.x * 256 + threadIdx.x;
    if (idx >= BSW_) return;
    const int w   = idx % W_;
    const int bs  = idx / W_;
    const int s   = bs % S_;
    const int b   = bs / S_;
    float v;
    if (s == 0) v = cls[w];
    else        v = tok[((size_t)b * NPATCH_ + (s - 1)) * W_ + w];
    h[idx] = v + pe[(size_t)s * W_ + w];
}

// ---------------- layernorm ----------------
__global__ void layernorm_kernel(const float* __restrict__ x,
                                 const float* __restrict__ gamma,
                                 const float* __restrict__ beta,
                                 float* __restrict__ y)
{
    const int row = blockIdx.x;
    const float* xr = x + (size_t)row * W_;
    float s = 0.f, s2 = 0.f;
    for (int i = threadIdx.x; i < W_; i += 256) {
        float v = xr[i];
        s += v; s2 += v * v;
    }
    for (int off = 16; off > 0; off >>= 1) {
        s  += __shfl_down_sync(0xffffffffu, s, off);
        s2 += __shfl_down_sync(0xffffffffu, s2, off);
    }
    __shared__ float rs[8], rs2[8];
    const int warp = threadIdx.x >> 5, lane = threadIdx.x & 31;
    if (lane == 0) { rs[warp] = s; rs2[warp] = s2; }
    __syncthreads();
    __shared__ float mean_sh, inv_sh;
    if (threadIdx.x == 0) {
        float ts = 0.f, ts2 = 0.f;
        for (int i = 0; i < 8; i++) { ts += rs[i]; ts2 += rs2[i]; }
        float mean = ts * (1.0f / W_);
        float var  = ts2 * (1.0f / W_) - mean * mean;
        mean_sh = mean;
        inv_sh  = rsqrtf(var + 1e-5f);
    }
    __syncthreads();
    const float mean = mean_sh, inv = inv_sh;
    float* yr = y + (size_t)row * W_;
    for (int i = threadIdx.x; i < W_; i += 256)
        yr[i] = (xr[i] - mean) * inv * gamma[i] + beta[i];
}

// ---------------- attention: scores = q . k^T ----------------
__global__ void attn_scores_kernel(const float* __restrict__ q,
                                   const float* __restrict__ k,
                                   float* __restrict__ att)
{
    const int z  = blockIdx.z;
    const int b  = z / H_, h = z % H_;
    const int s0 = blockIdx.y * 16;
    const int t0 = blockIdx.x * 16;

    __shared__ float qs[16][65];
    __shared__ float ks[16][65];

    const int t = threadIdx.x;
    const int r = t >> 4;
    const int c = (t & 15) * 4;

    const float* qbase = q + (size_t)b * S_ * W_ + h * HD_;
    const float* kbase = k + (size_t)b * S_ * W_ + h * HD_;

    const int gs = s0 + r;
    float4 qv = (gs < S_) ? *reinterpret_cast<const float4*>(qbase + (size_t)gs * W_ + c)
                          : make_float4(0.f, 0.f, 0.f, 0.f);
    qs[r][c] = qv.x; qs[r][c + 1] = qv.y; qs[r][c + 2] = qv.z; qs[r][c + 3] = qv.w;

    const int gt = t0 + r;
    float4 kv = (gt < S_) ? *reinterpret_cast<const float4*>(kbase + (size_t)gt * W_ + c)
                          : make_float4(0.f, 0.f, 0.f, 0.f);
    ks[r][c] = kv.x; ks[r][c + 1] = kv.y; ks[r][c + 2] = kv.z; ks[r][c + 3] = kv.w;
    __syncthreads();

    const int si = t >> 4, ti = t & 15;
    float acc = 0.f;
    #pragma unroll
    for (int d = 0; d < HD_; d++)
        acc = fmaf(qs[si][d], ks[ti][d], acc);

    const int gs2 = s0 + si, gt2 = t0 + ti;
    if (gs2 < S_ && gt2 < S_)
        att[((size_t)z * S_ + gs2) * S_ + gt2] = acc;
}

// ---------------- softmax (scale folded) ----------------
__global__ void softmax_kernel(float* __restrict__ att, int nrows)
{
    const int warp = blockIdx.x * 4 + (threadIdx.x >> 5);
    const int lane = threadIdx.x & 31;
    if (warp >= nrows) return;
    float* row = att + (size_t)warp * S_;

    float mx = -1e30f;
    for (int i = lane; i < S_; i += 32) mx = fmaxf(mx, row[i]);
    for (int off = 16; off > 0; off >>= 1)
        mx = fmaxf(mx, __shfl_xor_sync(0xffffffffu, mx, off));

    float sum = 0.f;
    for (int i = lane; i < S_; i += 32) {
        float e = expf((row[i] - mx) * 0.125f);
        row[i] = e;
        sum += e;
    }
    for (int off = 16; off > 0; off >>= 1)
        sum += __shfl_xor_sync(0xffffffffu, sum, off);
    const float inv = 1.0f / sum;
    for (int i = lane; i < S_; i += 32) row[i] *= inv;
}

// ---------------- o = att @ v ----------------
__global__ void attn_av_kernel(const float* __restrict__ att,
                               const float* __restrict__ v,
                               float* __restrict__ o)
{
    const int z  = blockIdx.y;
    const int b  = z / H_, h = z % H_;
    const int s0 = blockIdx.x * 16;

    __shared__ float as_[16][17];
    __shared__ float vs[16][65];

    const int si = threadIdx.x >> 4;
    const int dj = threadIdx.x & 15;

    float acc0 = 0.f, acc1 = 0.f, acc2 = 0.f, acc3 = 0.f;
    const float* vbase = v + (size_t)b * S_ * W_ + h * HD_;

    for (int t0 = 0; t0 < S_; t0 += 16) {
        float a = 0.f;
        if (s0 + si < S_ && t0 + dj < S_)
            a = att[((size_t)z * S_ + s0 + si) * S_ + t0 + dj];
        as_[si][dj] = a;

        const int r = si, c = dj * 4;
        float4 vv = (t0 + r < S_) ? *reinterpret_cast<const float4*>(vbase + (size_t)(t0 + r) * W_ + c)
                                  : make_float4(0.f, 0.f, 0.f, 0.f);
        vs[r][c] = vv.x; vs[r][c + 1] = vv.y; vs[r][c + 2] = vv.z; vs[r][c + 3] = vv.w;
        __syncthreads();

        #pragma unroll
        for (int tt = 0; tt < 16; tt++) {
            const float a2 = as_[si][tt];
            acc0 = fmaf(a2, vs[tt][dj * 4 + 0], acc0);
            acc1 = fmaf(a2, vs[tt][dj * 4 + 1], acc1);
            acc2 = fmaf(a2, vs[tt][dj * 4 + 2], acc2);
            acc3 = fmaf(a2, vs[tt][dj * 4 + 3], acc3);
        }
        __syncthreads();
    }

    const int gs = s0 + si;
    if (gs < S_) {
        float* obase = o + (size_t)b * S_ * W_ + (size_t)gs * W_ + h * HD_ + dj * 4;
        obase[0] = acc0; obase[1] = acc1; obase[2] = acc2; obase[3] = acc3;
    }
}

// ---------------- gather h[:,0,:] ----------------
__global__ void gather_cls_kernel(const float* __restrict__ h, float* __restrict__ cls)
{
    int idx = blockIdx.x * 256 + threadIdx.x;
    if (idx >= B_ * W_) return;
    const int b = idx / W_, w = idx % W_;
    cls[idx] = h[(size_t)b * S_ * W_ + w];
}

// ---------------- L2 normalize ----------------
__global__ void l2norm_kernel(float* __restrict__ out)
{
    const int row = blockIdx.x;
    float* r = out + (size_t)row * E_;
    float s = 0.f;
    for (int i = threadIdx.x; i < E_; i += 256) { float v = r[i]; s += v * v; }
    for (int off = 16; off > 0; off >>= 1) s += __shfl_down_sync(0xffffffffu, s, off);
    __shared__ float rs[8];
    const int warp = threadIdx.x >> 5, lane = threadIdx.x & 31;
    if (lane == 0) rs[warp] = s;
    __syncthreads();
    __shared__ float inv_sh;
    if (threadIdx.x == 0) {
        float ts = 0.f;
        for (int i = 0; i < 8; i++) ts += rs[i];
        inv_sh = rsqrtf(ts);
    }
    __syncthreads();
    const float inv = inv_sh;
    for (int i = threadIdx.x; i < E_; i += 256) r[i] *= inv;
}

// ---------------- launch ----------------
extern "C" void kernel_launch(void* const* d_in, const int* in_sizes, int n_in,
                              void* d_out, int out_size)
{
    (void)in_sizes; (void)n_in; (void)out_size;

    const float* x       = (const float*)d_in[0];
    const float* conv_w  = (const float*)d_in[1];
    const float* conv_b  = (const float*)d_in[2];
    const float* cls_tok = (const float*)d_in[3];
    const float* pe      = (const float*)d_in[4];
    const float* ln1_g   = (const float*)d_in[5];
    const float* ln1_b   = (const float*)d_in[6];
    const float* wq      = (const float*)d_in[7];
    const float* bq      = (const float*)d_in[8];
    const float* wk      = (const float*)d_in[9];
    const float* bk      = (const float*)d_in[10];
    const float* wv      = (const float*)d_in[11];
    const float* bv      = (const float*)d_in[12];
    const float* wo      = (const float*)d_in[13];
    const float* bo      = (const float*)d_in[14];
    const float* ln2_g   = (const float*)d_in[15];
    const float* ln2_b   = (const float*)d_in[16];
    const float* w1      = (const float*)d_in[17];
    const float* b1      = (const float*)d_in[18];
    const float* w2      = (const float*)d_in[19];
    const float* b2      = (const float*)d_in[20];
    const float* proj    = (const float*)d_in[21];
    float* out           = (float*)d_out;

    float *h, *y, *q, *k, *v, *o, *att, *ff, *i2c, *tok, *cls;
    cudaGetSymbolAddress((void**)&h,   g_h);
    cudaGetSymbolAddress((void**)&y,   g_y);
    cudaGetSymbolAddress((void**)&q,   g_q);
    cudaGetSymbolAddress((void**)&k,   g_k);
    cudaGetSymbolAddress((void**)&v,   g_v);
    cudaGetSymbolAddress((void**)&o,   g_o);
    cudaGetSymbolAddress((void**)&att, g_att);
    cudaGetSymbolAddress((void**)&ff,  g_ff);
    cudaGetSymbolAddress((void**)&i2c, g_im2col);
    cudaGetSymbolAddress((void**)&tok, g_tok);
    cudaGetSymbolAddress((void**)&cls, g_cls);

    const int M  = B_ * S_;          // 6304
    const int Mp = B_ * NPATCH_;     // 6272

    // --- patch embedding ---
    {
        const int total = Mp * W_;
        im2col_kernel<<<(total + 255) / 256, 256>>>(x, i2c);
        dim3 grid(W_ / 128, (Mp + 127) / 128);
        gemm_tc<1, 1, 0, 0><<<grid, 256>>>(i2c, conv_w, conv_b, tok, Mp, W_, W_);
        assemble_kernel<<<(BSW_ + 255) / 256, 256>>>(tok, cls_tok, pe, h);
    }

    const int nrows_att = B_ * H_ * S_;
    dim3 gridW (W_  / 128, (M + 127) / 128);   // (6, 50)
    dim3 gridFF(FF_ / 128, (M + 127) / 128);   // (24, 50)
    dim3 gridSc(13, 13, B_ * H_);
    dim3 gridAv(13, B_ * H_);

    for (int l = 0; l < L_; l++) {
        const size_t wOff = (size_t)l * W_ * W_;
        const size_t bOff = (size_t)l * W_;

        layernorm_kernel<<<M, 256>>>(h, ln1_g + bOff, ln1_b + bOff, y);
        gemm_tc<0, 1, 0, 0><<<gridW, 256>>>(y, wq + wOff, bq + bOff, q, M, W_, W_);
        gemm_tc<0, 1, 0, 0><<<gridW, 256>>>(y, wk + wOff, bk + bOff, k, M, W_, W_);
        gemm_tc<0, 1, 0, 0><<<gridW, 256>>>(y, wv + wOff, bv + bOff, v, M, W_, W_);
        attn_scores_kernel<<<gridSc, 256>>>(q, k, att);
        softmax_kernel<<<(nrows_att + 3) / 4, 128>>>(att, nrows_att);
        attn_av_kernel<<<gridAv, 256>>>(att, v, o);
        gemm_tc<0, 1, 1, 0><<<gridW, 256>>>(o, wo + wOff, bo + bOff, h, M, W_, W_);
        layernorm_kernel<<<M, 256>>>(h, ln2_g + bOff, ln2_b + bOff, y);
        gemm_tc<0, 1, 0, 1><<<gridFF, 256>>>(y, w1 + (size_t)l * W_ * FF_,
                                             b1 + (size_t)l * FF_, ff, M, FF_, W_);
        gemm_tc<0, 1, 1, 0><<<gridW, 256>>>(ff, w2 + (size_t)l * FF_ * W_,
                                            b2 + bOff, h, M, W_, FF_);
    }

    gather_cls_kernel<<<(B_ * W_ + 255) / 256, 256>>>(h, cls);
    {
        dim3 grid(E_ / 128, 1);
        gemm_tc<0, 0, 0, 0><<<grid, 256>>>(cls, proj, nullptr, out, B_, E_, W_);
    }
    l2norm_kernel<<<B_, 256>>>(out);
}